// round 1
// baseline (speedup 1.0000x reference)
#include <cuda_runtime.h>

// TransD scoring: out = h - t + r + rp * ((hp.h) - (tp.t))
// One warp per row. lane i handles elements [4i, 4i+4) as a float4.
// B = 262144, D = 128 (D/4 = 32 float4 per row == warp width).

static constexpr int DV4 = 32;  // 128 floats / 4

__global__ __launch_bounds__(256) void transd_kernel(
    const int* __restrict__ head,
    const int* __restrict__ relation,
    const int* __restrict__ tail,
    const float4* __restrict__ ent_emb,
    const float4* __restrict__ ent_map_emb,
    const float4* __restrict__ rel_emb,
    const float4* __restrict__ rel_map_emb,
    float4* __restrict__ out,
    int B)
{
    int gtid = blockIdx.x * blockDim.x + threadIdx.x;
    int row  = gtid >> 5;
    int lane = gtid & 31;
    if (row >= B) return;

    // Index loads: all lanes read same address -> broadcast, L1/L2 hit.
    int hi = __ldg(&head[row]);
    int ri = __ldg(&relation[row]);
    int ti = __ldg(&tail[row]);

    long hoff = (long)hi * DV4 + lane;
    long toff = (long)ti * DV4 + lane;
    long roff = (long)ri * DV4 + lane;

    // Front-batch all 6 independent loads for max MLP.
    float4 hv = __ldg(&ent_emb[hoff]);
    float4 hp = __ldg(&ent_map_emb[hoff]);
    float4 tv = __ldg(&ent_emb[toff]);
    float4 tp = __ldg(&ent_map_emb[toff]);
    float4 rv = __ldg(&rel_emb[roff]);
    float4 rp = __ldg(&rel_map_emb[roff]);

    // Per-lane partial dot products.
    float sh = hv.x * hp.x + hv.y * hp.y + hv.z * hp.z + hv.w * hp.w;
    float st = tv.x * tp.x + tv.y * tp.y + tv.z * tp.z + tv.w * tp.w;

    // Warp butterfly reduction (both sums interleaved).
    #pragma unroll
    for (int o = 16; o > 0; o >>= 1) {
        sh += __shfl_xor_sync(0xffffffffu, sh, o);
        st += __shfl_xor_sync(0xffffffffu, st, o);
    }
    float s = sh - st;

    float4 o4;
    o4.x = hv.x - tv.x + rv.x + rp.x * s;
    o4.y = hv.y - tv.y + rv.y + rp.y * s;
    o4.z = hv.z - tv.z + rv.z + rp.z * s;
    o4.w = hv.w - tv.w + rv.w + rp.w * s;

    out[(long)row * DV4 + lane] = o4;
}

extern "C" void kernel_launch(void* const* d_in, const int* in_sizes, int n_in,
                              void* d_out, int out_size)
{
    const int*    head    = (const int*)d_in[0];
    const int*    rel     = (const int*)d_in[1];
    const int*    tail    = (const int*)d_in[2];
    const float4* ent     = (const float4*)d_in[3];
    const float4* ent_map = (const float4*)d_in[4];
    const float4* rel_e   = (const float4*)d_in[5];
    const float4* rel_map = (const float4*)d_in[6];
    float4*       out     = (float4*)d_out;

    int B = in_sizes[0];
    // 256 threads = 8 warps = 8 rows per block
    int blocks = (B + 7) / 8;
    transd_kernel<<<blocks, 256>>>(head, rel, tail, ent, ent_map, rel_e, rel_map, out, B);
}